// round 15
// baseline (speedup 1.0000x reference)
#include <cuda_runtime.h>
#include <cuda_bf16.h>
#include <math.h>
#include <stdint.h>

#define B_  4
#define L_  2048
#define H_  512
#define N_  8
#define D_  64
#define M_  (B_*L_)   // 8192 rows
#define HW  256       // H_/2 words per row (bf16x2)

// ---------------- scratch ----------------
__device__ uint32_t g_qc[M_*HW];   // bf16x2
__device__ uint32_t g_qp[M_*HW];
__device__ uint32_t g_k [M_*HW];
__device__ uint32_t g_v [M_*HW];
__device__ uint32_t g_r [L_*HW];
__device__ float g_attn[M_*H_];
__device__ float g_t1  [M_*H_];
__device__ float g_a   [M_*H_];
__device__ float g_h1  [M_*H_];
__device__ float g_h2  [M_*H_];

// ---------------- helpers ----------------
__device__ __forceinline__ uint32_t fbits(float x) { return __float_as_uint(x); }
__device__ __forceinline__ uint32_t bf2(float x, float y) {
    __nv_bfloat162 t = __floats2bfloat162_rn(x, y);
    return *(uint32_t*)&t;
}
__device__ __forceinline__ float bfu(uint16_t h) {
    return __uint_as_float(((uint32_t)h) << 16);
}
__device__ __forceinline__ void cpa16(void* dst, const void* src) {
    uint32_t d = (uint32_t)__cvta_generic_to_shared(dst);
    asm volatile("cp.async.ca.shared.global [%0], [%1], 16;" :: "r"(d), "l"(src));
}
#define CPA_COMMIT() asm volatile("cp.async.commit_group;")
#define CPA_WAIT1()  asm volatile("cp.async.wait_group 1;")
#define CPA_WAIT0()  asm volatile("cp.async.wait_group 0;")

__device__ __forceinline__ void mma_tf32(float* c,
                                         uint32_t a0, uint32_t a1, uint32_t a2, uint32_t a3,
                                         uint32_t b0, uint32_t b1) {
    asm("mma.sync.aligned.m16n8k8.row.col.f32.tf32.tf32.f32 "
        "{%0,%1,%2,%3}, {%4,%5,%6,%7}, {%8,%9}, {%0,%1,%2,%3};"
        : "+f"(c[0]), "+f"(c[1]), "+f"(c[2]), "+f"(c[3])
        : "r"(a0), "r"(a1), "r"(a2), "r"(a3), "r"(b0), "r"(b1));
}
__device__ __forceinline__ void mma_bf16(float* c,
                                         uint32_t a0, uint32_t a1, uint32_t a2, uint32_t a3,
                                         uint32_t b0, uint32_t b1) {
    asm("mma.sync.aligned.m16n8k16.row.col.f32.bf16.bf16.f32 "
        "{%0,%1,%2,%3}, {%4,%5,%6,%7}, {%8,%9}, {%0,%1,%2,%3};"
        : "+f"(c[0]), "+f"(c[1]), "+f"(c[2]), "+f"(c[3])
        : "r"(a0), "r"(a1), "r"(a2), "r"(a3), "r"(b0), "r"(b1));
}
__device__ __forceinline__ void ldsm4(uint32_t* r, uint32_t a) {
    asm volatile("ldmatrix.sync.aligned.m8n8.x4.shared.b16 {%0,%1,%2,%3}, [%4];"
        : "=r"(r[0]), "=r"(r[1]), "=r"(r[2]), "=r"(r[3]) : "r"(a));
}
__device__ __forceinline__ void ldsm4t(uint32_t* r, uint32_t a) {
    asm volatile("ldmatrix.sync.aligned.m8n8.x4.trans.shared.b16 {%0,%1,%2,%3}, [%4];"
        : "=r"(r[0]), "=r"(r[1]), "=r"(r[2]), "=r"(r[3]) : "r"(a));
}

// ---------------- fused projection GEMM: QKV (x) + R (pe), tf32 ----------------
__global__ __launch_bounds__(256)
void proj_kernel(const float* __restrict__ x, const float* __restrict__ pe,
                 const float* __restrict__ Wq, const float* __restrict__ bq,
                 const float* __restrict__ cb, const float* __restrict__ pb,
                 const float* __restrict__ Wk, const float* __restrict__ bk,
                 const float* __restrict__ Wv, const float* __restrict__ bv,
                 const float* __restrict__ Wr, const float* __restrict__ br,
                 uint32_t* __restrict__ qcP, uint32_t* __restrict__ qpP,
                 uint32_t* __restrict__ kP, uint32_t* __restrict__ vP,
                 uint32_t* __restrict__ rP)
{
    __shared__ float As[2][128][20];
    __shared__ float Bsm[2][2560];
    const int tid  = threadIdx.x;
    const int lane = tid & 31;
    const int w    = tid >> 5;
    const int rw64 = (w >> 2) << 6;
    const int cw32 = (w & 3) << 5;
    const int lq = lane >> 2;
    const int lr = lane & 3;
    const int K = H_;

    int bx = blockIdx.x;
    int m0, cg;
    const float* A;
    if (bx < 768) { m0 = (bx / 12) << 7; cg = (bx % 12) << 7; A = x; }
    else { int t = bx - 768; m0 = (t >> 2) << 7; cg = ((t & 3) << 7) + 1536; A = pe; }
    const int seg = cg >> 9;          // 0=q 1=k 2=v 3=r
    const int c0  = cg & 511;
    const float* W    = (seg == 0) ? Wq : (seg == 1) ? Wk : (seg == 2) ? Wv : Wr;
    const float* bias = (seg == 0) ? bq : (seg == 1) ? bk : (seg == 2) ? bv : br;
    uint32_t* o1 = (seg == 0) ? qcP : (seg == 1) ? kP : (seg == 2) ? vP : rP;

    float C[4][4][4];
#pragma unroll
    for (int mt = 0; mt < 4; mt++)
#pragma unroll
        for (int nt = 0; nt < 4; nt++)
#pragma unroll
            for (int e = 0; e < 4; e++) C[mt][nt][e] = 0.f;

    const int arow0 = tid >> 2, aq0 = (tid & 3) << 2;
    const int arow1 = (tid + 256) >> 2, aq1 = ((tid + 256) & 3) << 2;

    auto load_chunk = [&](int st, int k0) {
        cpa16(&As[st][arow0][aq0], A + (size_t)(m0 + arow0) * K + k0 + aq0);
        cpa16(&As[st][arow1][aq1], A + (size_t)(m0 + arow1) * K + k0 + aq1);
#pragma unroll
        for (int jj = 0; jj < 2; jj++) {
            int f = tid + jj * 256;
            int kk = f >> 5, c4 = (f & 31) << 2;
            int cc = c0 + c4;
            cpa16(&Bsm[st][kk * 136 + c4],
                  W + (size_t)(cc >> 6) * ((size_t)K * 64)
                    + (size_t)(k0 + kk) * 64 + (cc & 63));
        }
    };

    const int NCH = K >> 4;
    load_chunk(0, 0);
    CPA_COMMIT();

    for (int ch = 0; ch < NCH; ch++) {
        if (ch + 1 < NCH) {
            load_chunk((ch + 1) & 1, (ch + 1) << 4);
            CPA_COMMIT();
            CPA_WAIT1();
        } else {
            CPA_WAIT0();
        }
        __syncthreads();
        const int st = ch & 1;
#pragma unroll
        for (int kc = 0; kc < 16; kc += 8) {
            uint32_t bf[4][2];
#pragma unroll
            for (int nt = 0; nt < 4; nt++) {
                int n = cw32 + 8 * nt + lq;
                bf[nt][0] = fbits(Bsm[st][(kc + lr) * 136 + n]);
                bf[nt][1] = fbits(Bsm[st][(kc + 4 + lr) * 136 + n]);
            }
#pragma unroll
            for (int mt = 0; mt < 4; mt++) {
                int i = rw64 + 16 * mt + lq;
                uint32_t a0 = fbits(As[st][i][kc + lr]);
                uint32_t a1 = fbits(As[st][i + 8][kc + lr]);
                uint32_t a2 = fbits(As[st][i][kc + 4 + lr]);
                uint32_t a3 = fbits(As[st][i + 8][kc + 4 + lr]);
#pragma unroll
                for (int nt = 0; nt < 4; nt++)
                    mma_tf32(C[mt][nt], a0, a1, a2, a3, bf[nt][0], bf[nt][1]);
            }
        }
        __syncthreads();
    }

#pragma unroll
    for (int mt = 0; mt < 4; mt++) {
        int m = m0 + rw64 + 16 * mt + lq;
#pragma unroll
        for (int nt = 0; nt < 4; nt++) {
            int c = c0 + cw32 + 8 * nt + 2 * lr;
            float b0 = bias[c], b1 = bias[c + 1];
            float v00 = C[mt][nt][0] + b0, v01 = C[mt][nt][1] + b1;
            float v10 = C[mt][nt][2] + b0, v11 = C[mt][nt][3] + b1;
            size_t w0 = (size_t)m * HW + (c >> 1), w1 = w0 + (size_t)8 * HW;
            if (seg == 0) {
                float c20 = cb[c], c21 = cb[c + 1];
                float p20 = pb[c], p21 = pb[c + 1];
                o1[w0]  = bf2(v00 + c20, v01 + c21);
                o1[w1]  = bf2(v10 + c20, v11 + c21);
                qpP[w0] = bf2(v00 + p20, v01 + p21);
                qpP[w1] = bf2(v10 + p20, v11 + p21);
            } else {
                o1[w0] = bf2(v00, v01);
                o1[w1] = bf2(v10, v11);
            }
        }
    }
}

// ---------------- GEMM (tf32, cp.async double-buffered) for Wc/W1/W2 ----------------
enum { EPI_BIAS = 0, EPI_GELU = 2 };

template<int EPI>
__global__ __launch_bounds__(256)
void gemm_kernel(const float* __restrict__ A, const float* __restrict__ W,
                 const float* __restrict__ bias,
                 float* __restrict__ out1, int M, int N, int K)
{
    __shared__ float As[2][128][20];
    __shared__ float Bsm[2][2560];
    const int tid  = threadIdx.x;
    const int lane = tid & 31;
    const int w    = tid >> 5;
    const int rw64 = (w >> 2) << 6;
    const int cw32 = (w & 3) << 5;
    const int m0 = blockIdx.y << 7, c0 = blockIdx.x << 7;
    const int lq = lane >> 2;
    const int lr = lane & 3;

    float C[4][4][4];
#pragma unroll
    for (int mt = 0; mt < 4; mt++)
#pragma unroll
        for (int nt = 0; nt < 4; nt++)
#pragma unroll
            for (int e = 0; e < 4; e++) C[mt][nt][e] = 0.f;

    const int arow0 = tid >> 2, aq0 = (tid & 3) << 2;
    const int arow1 = (tid + 256) >> 2, aq1 = ((tid + 256) & 3) << 2;

    auto load_chunk = [&](int st, int k0) {
        cpa16(&As[st][arow0][aq0], A + (size_t)(m0 + arow0) * K + k0 + aq0);
        cpa16(&As[st][arow1][aq1], A + (size_t)(m0 + arow1) * K + k0 + aq1);
#pragma unroll
        for (int jj = 0; jj < 2; jj++) {
            int f = tid + jj * 256;
            int c = f >> 2, q = (f & 3) << 2;
            cpa16(&Bsm[st][c * 20 + q], W + (size_t)(c0 + c) * K + k0 + q);
        }
    };

    const int NCH = K >> 4;
    load_chunk(0, 0);
    CPA_COMMIT();

    for (int ch = 0; ch < NCH; ch++) {
        if (ch + 1 < NCH) {
            load_chunk((ch + 1) & 1, (ch + 1) << 4);
            CPA_COMMIT();
            CPA_WAIT1();
        } else {
            CPA_WAIT0();
        }
        __syncthreads();
        const int st = ch & 1;
#pragma unroll
        for (int kc = 0; kc < 16; kc += 8) {
            uint32_t bf[4][2];
#pragma unroll
            for (int nt = 0; nt < 4; nt++) {
                int n = cw32 + 8 * nt + lq;
                bf[nt][0] = fbits(Bsm[st][n * 20 + kc + lr]);
                bf[nt][1] = fbits(Bsm[st][n * 20 + kc + 4 + lr]);
            }
#pragma unroll
            for (int mt = 0; mt < 4; mt++) {
                int i = rw64 + 16 * mt + lq;
                uint32_t a0 = fbits(As[st][i][kc + lr]);
                uint32_t a1 = fbits(As[st][i + 8][kc + lr]);
                uint32_t a2 = fbits(As[st][i][kc + 4 + lr]);
                uint32_t a3 = fbits(As[st][i + 8][kc + 4 + lr]);
#pragma unroll
                for (int nt = 0; nt < 4; nt++)
                    mma_tf32(C[mt][nt], a0, a1, a2, a3, bf[nt][0], bf[nt][1]);
            }
        }
        __syncthreads();
    }

#pragma unroll
    for (int mt = 0; mt < 4; mt++) {
        int m = m0 + rw64 + 16 * mt + lq;
#pragma unroll
        for (int nt = 0; nt < 4; nt++) {
            int c = c0 + cw32 + 8 * nt + 2 * lr;
            float b0 = bias[c], b1 = bias[c + 1];
            float v00 = C[mt][nt][0] + b0, v01 = C[mt][nt][1] + b1;
            float v10 = C[mt][nt][2] + b0, v11 = C[mt][nt][3] + b1;
            size_t o0 = (size_t)m * N + c, o1 = o0 + (size_t)8 * N;
            if (EPI == EPI_GELU) {
                v00 = v00 * 0.5f * (1.f + erff(v00 * 0.70710678118654752f));
                v01 = v01 * 0.5f * (1.f + erff(v01 * 0.70710678118654752f));
                v10 = v10 * 0.5f * (1.f + erff(v10 * 0.70710678118654752f));
                v11 = v11 * 0.5f * (1.f + erff(v11 * 0.70710678118654752f));
            }
            *(float2*)(out1 + o0) = make_float2(v00, v01);
            *(float2*)(out1 + o1) = make_float2(v10, v11);
        }
    }
}

// ---------------- flash attention v4: halo sp ring (wrap-free gather) ----------------
#define WST 36           // row stride (words) for qc/qp/K/V/r tiles
#define SPW 128          // sp row stride (words): 256 hw slots (192 + 63 halo)
// word offsets
#define K_O  0           // 2 stages x 2304
#define V_O  4608        // 2 stages x 2304
#define R_O  9216        // 192 x 36
#define SP_O 16128       // 64 x 128
#define QC_O SP_O        // prologue-only staging (dead after fragment hoist)
#define QP_O (SP_O + 2304)
#define SM_WORDS 24320
#define ATTN_SMEM_BYTES (SM_WORDS * 4)   // 97280

__global__ __launch_bounds__(256, 2)
void attn_kernel(const uint32_t* __restrict__ qcg, const uint32_t* __restrict__ qpg,
                 const uint32_t* __restrict__ kg, const uint32_t* __restrict__ vg,
                 const uint32_t* __restrict__ rg, float* __restrict__ out)
{
    extern __shared__ uint32_t sm[];
    const uint32_t sbase = (uint32_t)__cvta_generic_to_shared(sm);
    uint16_t* sp16 = (uint16_t*)(sm + SP_O);

    const int tid  = threadIdx.x;
    const int lane = tid & 31;
    const int w    = tid >> 5;
    const bool comp = (w < 4);
    const int lq = lane >> 2, lr = lane & 3;
    const int lt = lane >> 3, lu = lane & 7;
    const int bn  = (lt >> 1) * 8 + lu;
    const int bk  = (lt & 1) * 4;
    const int vj  = (lt & 1) * 8 + lu;
    const int vd4 = (lt >> 1) * 4;
    const int ar  = (lt & 1) * 8 + lu;
    const int ak  = (lt >> 1) * 4;

    const int bh = blockIdx.y;
    const int b  = bh >> 3, n = bh & 7;
    const int i0 = ((int)gridDim.x - 1 - (int)blockIdx.x) << 6;
    const int colw = n << 5;
    const size_t rowb = (size_t)(b * L_);
    const int ni = (i0 >> 6) + 1;
    const int bl0 = 1984 - i0;

    // ---- prologue loads: qc/qp (staged in sp region), K(0), V(0), r blocks 0..2
#pragma unroll
    for (int g = 0; g < 2; g++) {
        int idx = tid + 256 * g;
        int row = idx >> 3, gg = (idx & 7) << 2;
        cpa16(sm + QC_O + row * WST + gg, qcg + (rowb + i0 + row) * HW + colw + gg);
        cpa16(sm + QP_O + row * WST + gg, qpg + (rowb + i0 + row) * HW + colw + gg);
        cpa16(sm + K_O + row * WST + gg,  kg  + (rowb + row) * HW + colw + gg);
        cpa16(sm + V_O + row * WST + gg,  vg  + (rowb + row) * HW + colw + gg);
    }
#pragma unroll
    for (int g = 0; g < 6; g++) {
        int idx = tid + 256 * g;
        int row = idx >> 3, gg = (idx & 7) << 2;
        int p = bl0 + row;
        uint32_t* dst = sm + R_O + (p % 192) * WST + gg;
        if (p < L_) cpa16(dst, rg + (size_t)p * HW + colw + gg);
        else        *(uint4*)dst = make_uint4(0, 0, 0, 0);
    }
    CPA_COMMIT();
    CPA_WAIT0();
    __syncthreads();

    // ---- loop-invariant A fragments (comp: qc; helper: qp)
    uint32_t aqf[4][4];
    {
        const uint32_t abase = sbase + (comp ? QC_O : QP_O) * 4;
        const int arow = ((comp ? (w & 3) : (w - 4)) << 4) + ar;
#pragma unroll
        for (int k4 = 0; k4 < 4; k4++)
            ldsm4(aqf[k4], abase + (uint32_t)(arow * WST + k4 * 8 + ak) * 4);
    }
    __syncthreads();   // hoist done before sp region overwritten

    const int hrow = ((w - 4) & 3) << 4;
    auto sp_block = [&](int bidx) {
        const int slotb = (bl0 + 64 * bidx) % 192;
        float SP[8][4];
#pragma unroll
        for (int nt = 0; nt < 8; nt++)
#pragma unroll
            for (int e = 0; e < 4; e++) SP[nt][e] = 0.f;
#pragma unroll
        for (int k4 = 0; k4 < 4; k4++) {
#pragma unroll
            for (int ntp = 0; ntp < 4; ntp++) {
                uint32_t bb[4];
                ldsm4(bb, sbase + (uint32_t)(R_O + (slotb + 16 * ntp + bn) * WST
                                             + k4 * 8 + bk) * 4);
                mma_bf16(SP[2 * ntp],     aqf[k4][0], aqf[k4][1], aqf[k4][2], aqf[k4][3],
                         bb[0], bb[1]);
                mma_bf16(SP[2 * ntp + 1], aqf[k4][0], aqf[k4][1], aqf[k4][2], aqf[k4][3],
                         bb[2], bb[3]);
            }
        }
        const int ja = hrow + lq, jb = ja + 8;
        const bool halo = (slotb == 0);
#pragma unroll
        for (int nt = 0; nt < 8; nt++) {
            int sw_ = (slotb + 8 * nt + 2 * lr) >> 1;
            uint32_t va = bf2(SP[nt][0], SP[nt][1]);
            uint32_t vb = bf2(SP[nt][2], SP[nt][3]);
            sm[SP_O + ja * SPW + sw_] = va;
            sm[SP_O + jb * SPW + sw_] = vb;
            if (halo) {
                sm[SP_O + ja * SPW + sw_ + 96] = va;
                sm[SP_O + jb * SPW + sw_ + 96] = vb;
            }
        }
    };

    if (!comp) { sp_block(0); sp_block(1); }

    float O[8][4];
    float l_lo = 0.f, l_hi = 0.f;
#pragma unroll
    for (int nt = 0; nt < 8; nt++)
#pragma unroll
        for (int e = 0; e < 4; e++) O[nt][e] = 0.f;
    const int ia = ((w & 3) << 4) + lq, ib = ia + 8;
    const int t2 = tid & 127;

    for (int ch = 0; ch < ni; ch++) {
        __syncthreads();
        const int j0 = ch << 6;

        if (comp) {
            // ---- S = qc @ K^T
            const uint32_t kst = sbase + (uint32_t)(K_O + (ch & 1) * 2304) * 4;
            float S[8][4];
#pragma unroll
            for (int nt = 0; nt < 8; nt++)
#pragma unroll
                for (int e = 0; e < 4; e++) S[nt][e] = 0.f;
#pragma unroll
            for (int k4 = 0; k4 < 4; k4++) {
#pragma unroll
                for (int ntp = 0; ntp < 4; ntp++) {
                    uint32_t bb[4];
                    ldsm4(bb, kst + (uint32_t)((16 * ntp + bn) * WST + k4 * 8 + bk) * 4);
                    mma_bf16(S[2 * ntp],     aqf[k4][0], aqf[k4][1], aqf[k4][2], aqf[k4][3],
                             bb[0], bb[1]);
                    mma_bf16(S[2 * ntp + 1], aqf[k4][0], aqf[k4][1], aqf[k4][2], aqf[k4][3],
                             bb[2], bb[3]);
                }
            }
            // ---- wrap-free rel-shift gather + exp + pack P
            const int pb = (1984 + j0 - i0) % 192;       // in {0,64,128}
            const int base_lo = pb + 63 - ia;            // >= 0
            const int base_hi = base_lo - 8;             // >= 0
            const uint16_t* srow_lo = sp16 + ia * 256;
            const uint16_t* srow_hi = sp16 + ib * 256;
            const int thr = ia + (i0 - j0);
            uint32_t pk[8][2];
#pragma unroll
            for (int nt = 0; nt < 8; nt++) {
                int jl0 = 8 * nt + 2 * lr;
                float s0 = (S[nt][0] + bfu(srow_lo[base_lo + jl0]))     * 0.125f;
                float s1 = (S[nt][1] + bfu(srow_lo[base_lo + jl0 + 1])) * 0.125f;
                float s2 = (S[nt][2] + bfu(srow_hi[base_hi + jl0]))     * 0.125f;
                float s3 = (S[nt][3] + bfu(srow_hi[base_hi + jl0 + 1])) * 0.125f;
                float p0 = (jl0     <= thr)     ? __expf(s0) : 0.f;
                float p1 = (jl0 + 1 <= thr)     ? __expf(s1) : 0.f;
                float p2 = (jl0     <= thr + 8) ? __expf(s2) : 0.f;
                float p3 = (jl0 + 1 <= thr + 8) ? __expf(s3) : 0.f;
                l_lo += p0 + p1; l_hi += p2 + p3;
                pk[nt][0] = bf2(p0, p1);
                pk[nt][1] = bf2(p2, p3);
            }
            // ---- O += P @ V
            const uint32_t vst = sbase + (uint32_t)(V_O + (ch & 1) * 2304) * 4;
#pragma unroll
            for (int t4 = 0; t4 < 4; t4++) {
                uint32_t a0 = pk[2 * t4][0], a1 = pk[2 * t4][1];
                uint32_t a2 = pk[2 * t4 + 1][0], a3 = pk[2 * t4 + 1][1];
#pragma unroll
                for (int ntp = 0; ntp < 4; ntp++) {
                    uint32_t bb[4];
                    ldsm4t(bb, vst + (uint32_t)((t4 * 16 + vj) * WST + 8 * ntp + vd4) * 4);
                    mma_bf16(O[2 * ntp],     a0, a1, a2, a3, bb[0], bb[1]);
                    mma_bf16(O[2 * ntp + 1], a0, a1, a2, a3, bb[2], bb[3]);
                }
            }
        } else {
            if (ch + 2 <= ni) sp_block(ch + 2);
            if (ch + 1 < ni) {
#pragma unroll
                for (int g = 0; g < 4; g++) {
                    int idx = t2 + 128 * g;
                    int row = idx >> 3, gg = (idx & 7) << 2;
                    cpa16(sm + K_O + ((ch + 1) & 1) * 2304 + row * WST + gg,
                          kg + (rowb + j0 + 64 + row) * HW + colw + gg);
                    cpa16(sm + V_O + ((ch + 1) & 1) * 2304 + row * WST + gg,
                          vg + (rowb + j0 + 64 + row) * HW + colw + gg);
                }
                if (ch + 3 <= ni) {
#pragma unroll
                    for (int g = 0; g < 4; g++) {
                        int idx = t2 + 128 * g;
                        int row = idx >> 3, gg = (idx & 7) << 2;
                        int p = bl0 + 64 * (ch + 3) + row;
                        uint32_t* dst = sm + R_O + (p % 192) * WST + gg;
                        if (p < L_) cpa16(dst, rg + (size_t)p * HW + colw + gg);
                        else        *(uint4*)dst = make_uint4(0, 0, 0, 0);
                    }
                }
                CPA_COMMIT();
                CPA_WAIT0();
            }
        }
    }

    if (comp) {
        l_lo += __shfl_xor_sync(0xffffffffu, l_lo, 1);
        l_lo += __shfl_xor_sync(0xffffffffu, l_lo, 2);
        l_hi += __shfl_xor_sync(0xffffffffu, l_hi, 1);
        l_hi += __shfl_xor_sync(0xffffffffu, l_hi, 2);
        float la = 1.f / l_lo, lb = 1.f / l_hi;
        const size_t obase = (rowb + i0) * H_ + (n << 6);
#pragma unroll
        for (int nt = 0; nt < 8; nt++) {
            int cc = 8 * nt + 2 * lr;
            *(float2*)(out + obase + (size_t)ia * H_ + cc) =
                make_float2(O[nt][0] * la, O[nt][1] * la);
            *(float2*)(out + obase + (size_t)ib * H_ + cc) =
                make_float2(O[nt][2] * lb, O[nt][3] * lb);
        }
    }
}

// ---------------- fused residual-add + LayerNorm ----------------
__global__ __launch_bounds__(256)
void ln_kernel(const float* __restrict__ a, const float* __restrict__ b,
               const float* __restrict__ w, const float* __restrict__ beta,
               float* __restrict__ out)
{
    const int row = blockIdx.x;
    const int tid = threadIdx.x;
    const size_t base = (size_t)row * H_;
    float x0 = a[base + tid]       + b[base + tid];
    float x1 = a[base + tid + 256] + b[base + tid + 256];
    float s  = x0 + x1;
    float sq = x0 * x0 + x1 * x1;
#pragma unroll
    for (int o = 16; o > 0; o >>= 1) {
        s  += __shfl_xor_sync(0xffffffffu, s,  o);
        sq += __shfl_xor_sync(0xffffffffu, sq, o);
    }
    __shared__ float rs[8], rq[8];
    int wid = tid >> 5;
    if ((tid & 31) == 0) { rs[wid] = s; rq[wid] = sq; }
    __syncthreads();
    if (tid < 32) {
        float ss = (tid < 8) ? rs[tid] : 0.f;
        float qq = (tid < 8) ? rq[tid] : 0.f;
#pragma unroll
        for (int o = 4; o > 0; o >>= 1) {
            ss += __shfl_xor_sync(0xffffffffu, ss, o);
            qq += __shfl_xor_sync(0xffffffffu, qq, o);
        }
        if (tid == 0) { rs[0] = ss; rq[0] = qq; }
    }
    __syncthreads();
    float mean = rs[0] * (1.f / H_);
    float var  = rq[0] * (1.f / H_) - mean * mean;
    float inv  = rsqrtf(var + 1e-12f);
    out[base + tid]       = w[tid]       * (x0 - mean) * inv + beta[tid];
    out[base + tid + 256] = w[tid + 256] * (x1 - mean) * inv + beta[tid + 256];
}

// ---------------- launcher ----------------
extern "C" void kernel_launch(void* const* d_in, const int* in_sizes, int n_in,
                              void* d_out, int out_size)
{
    const float* x   = (const float*)d_in[0];
    const float* pe  = (const float*)d_in[1];
    const float* Wq  = (const float*)d_in[2];
    const float* bq  = (const float*)d_in[3];
    const float* Wk  = (const float*)d_in[4];
    const float* bk  = (const float*)d_in[5];
    const float* Wv  = (const float*)d_in[6];
    const float* bv  = (const float*)d_in[7];
    const float* Wr  = (const float*)d_in[8];
    const float* br  = (const float*)d_in[9];
    const float* cb  = (const float*)d_in[10];
    const float* pb  = (const float*)d_in[11];
    const float* Wc  = (const float*)d_in[12];
    const float* bc  = (const float*)d_in[13];
    const float* W1  = (const float*)d_in[14];
    const float* b1  = (const float*)d_in[15];
    const float* W2  = (const float*)d_in[16];
    const float* b2  = (const float*)d_in[17];
    const float* lnw = (const float*)d_in[18];
    const float* lnb = (const float*)d_in[19];
    float* out = (float*)d_out;

    uint32_t *qcP, *qpP, *kP, *vP, *rP;
    float *attnP, *t1P, *aP, *h1P, *h2P;
    cudaGetSymbolAddress((void**)&qcP,   g_qc);
    cudaGetSymbolAddress((void**)&qpP,   g_qp);
    cudaGetSymbolAddress((void**)&kP,    g_k);
    cudaGetSymbolAddress((void**)&vP,    g_v);
    cudaGetSymbolAddress((void**)&rP,    g_r);
    cudaGetSymbolAddress((void**)&attnP, g_attn);
    cudaGetSymbolAddress((void**)&t1P,   g_t1);
    cudaGetSymbolAddress((void**)&aP,    g_a);
    cudaGetSymbolAddress((void**)&h1P,   g_h1);
    cudaGetSymbolAddress((void**)&h2P,   g_h2);

    const dim3 gBig(H_ / 128, M_ / 128);   // (4, 64)

    proj_kernel<<<832, 256>>>(x, pe, Wq, bq, cb, pb, Wk, bk, Wv, bv, Wr, br,
                              qcP, qpP, kP, vP, rP);

    cudaFuncSetAttribute(attn_kernel, cudaFuncAttributeMaxDynamicSharedMemorySize, ATTN_SMEM_BYTES);
    attn_kernel<<<dim3(L_ / 64, B_ * N_), 256, ATTN_SMEM_BYTES>>>(qcP, qpP, kP, vP, rP, attnP);

    gemm_kernel<EPI_BIAS><<<gBig, 256>>>(attnP, Wc, bc, t1P, M_, H_, H_);
    ln_kernel<<<M_, 256>>>(t1P, x, lnw, lnb, aP);

    gemm_kernel<EPI_GELU><<<gBig, 256>>>(aP,  W1, b1, h1P, M_, H_, H_);
    gemm_kernel<EPI_BIAS><<<gBig, 256>>>(h1P, W2, b2, h2P, M_, H_, H_);
    ln_kernel<<<M_, 256>>>(aP, h2P, lnw, lnb, out);
}

// round 16
// speedup vs baseline: 1.1574x; 1.1574x over previous
#include <cuda_runtime.h>
#include <cuda_bf16.h>
#include <math.h>
#include <stdint.h>

#define B_  4
#define L_  2048
#define H_  512
#define N_  8
#define D_  64
#define M_  (B_*L_)   // 8192 rows
#define HW  256       // H_/2 words per row (bf16x2)

// ---------------- scratch ----------------
__device__ uint32_t g_qc[M_*HW];   // bf16x2 (reused as LN1 bf16 aux after attention)
__device__ uint32_t g_qp[M_*HW];
__device__ uint32_t g_k [M_*HW];   // reused as h1 bf16 after attention
__device__ uint32_t g_v [M_*HW];
__device__ uint32_t g_r [L_*HW];
__device__ float g_attn[M_*H_];    // attention out, bf16 words in first half
__device__ float g_t1  [M_*H_];
__device__ float g_a   [M_*H_];
__device__ float g_h2  [M_*H_];
__device__ uint32_t g_wcb[H_*HW];  // bf16 weights
__device__ uint32_t g_w1b[H_*HW];
__device__ uint32_t g_w2b[H_*HW];

// ---------------- helpers ----------------
__device__ __forceinline__ uint32_t fbits(float x) { return __float_as_uint(x); }
__device__ __forceinline__ uint32_t bf2(float x, float y) {
    __nv_bfloat162 t = __floats2bfloat162_rn(x, y);
    return *(uint32_t*)&t;
}
__device__ __forceinline__ float bfu(uint16_t h) {
    return __uint_as_float(((uint32_t)h) << 16);
}
__device__ __forceinline__ void cpa16(void* dst, const void* src) {
    uint32_t d = (uint32_t)__cvta_generic_to_shared(dst);
    asm volatile("cp.async.ca.shared.global [%0], [%1], 16;" :: "r"(d), "l"(src));
}
#define CPA_COMMIT() asm volatile("cp.async.commit_group;")
#define CPA_WAIT1()  asm volatile("cp.async.wait_group 1;")
#define CPA_WAIT0()  asm volatile("cp.async.wait_group 0;")

__device__ __forceinline__ void mma_tf32(float* c,
                                         uint32_t a0, uint32_t a1, uint32_t a2, uint32_t a3,
                                         uint32_t b0, uint32_t b1) {
    asm("mma.sync.aligned.m16n8k8.row.col.f32.tf32.tf32.f32 "
        "{%0,%1,%2,%3}, {%4,%5,%6,%7}, {%8,%9}, {%0,%1,%2,%3};"
        : "+f"(c[0]), "+f"(c[1]), "+f"(c[2]), "+f"(c[3])
        : "r"(a0), "r"(a1), "r"(a2), "r"(a3), "r"(b0), "r"(b1));
}
__device__ __forceinline__ void mma_bf16(float* c,
                                         uint32_t a0, uint32_t a1, uint32_t a2, uint32_t a3,
                                         uint32_t b0, uint32_t b1) {
    asm("mma.sync.aligned.m16n8k16.row.col.f32.bf16.bf16.f32 "
        "{%0,%1,%2,%3}, {%4,%5,%6,%7}, {%8,%9}, {%0,%1,%2,%3};"
        : "+f"(c[0]), "+f"(c[1]), "+f"(c[2]), "+f"(c[3])
        : "r"(a0), "r"(a1), "r"(a2), "r"(a3), "r"(b0), "r"(b1));
}
__device__ __forceinline__ void ldsm4(uint32_t* r, uint32_t a) {
    asm volatile("ldmatrix.sync.aligned.m8n8.x4.shared.b16 {%0,%1,%2,%3}, [%4];"
        : "=r"(r[0]), "=r"(r[1]), "=r"(r[2]), "=r"(r[3]) : "r"(a));
}
__device__ __forceinline__ void ldsm4t(uint32_t* r, uint32_t a) {
    asm volatile("ldmatrix.sync.aligned.m8n8.x4.trans.shared.b16 {%0,%1,%2,%3}, [%4];"
        : "=r"(r[0]), "=r"(r[1]), "=r"(r[2]), "=r"(r[3]) : "r"(a));
}

// ---------------- weight fp32 -> bf16 pack ----------------
__global__ __launch_bounds__(256)
void cvt_w_kernel(const float* __restrict__ Wc, const float* __restrict__ W1,
                  const float* __restrict__ W2,
                  uint32_t* __restrict__ wcb, uint32_t* __restrict__ w1b,
                  uint32_t* __restrict__ w2b)
{
    int i = blockIdx.x * 256 + threadIdx.x;     // < 131072
    float2 a = *(const float2*)(Wc + 2 * i);
    float2 b = *(const float2*)(W1 + 2 * i);
    float2 c = *(const float2*)(W2 + 2 * i);
    wcb[i] = bf2(a.x, a.y);
    w1b[i] = bf2(b.x, b.y);
    w2b[i] = bf2(c.x, c.y);
}

// ---------------- fused projection GEMM: QKV (x) + R (pe), tf32 ----------------
__global__ __launch_bounds__(256)
void proj_kernel(const float* __restrict__ x, const float* __restrict__ pe,
                 const float* __restrict__ Wq, const float* __restrict__ bq,
                 const float* __restrict__ cb, const float* __restrict__ pb,
                 const float* __restrict__ Wk, const float* __restrict__ bk,
                 const float* __restrict__ Wv, const float* __restrict__ bv,
                 const float* __restrict__ Wr, const float* __restrict__ br,
                 uint32_t* __restrict__ qcP, uint32_t* __restrict__ qpP,
                 uint32_t* __restrict__ kP, uint32_t* __restrict__ vP,
                 uint32_t* __restrict__ rP)
{
    __shared__ float As[2][128][20];
    __shared__ float Bsm[2][2560];
    const int tid  = threadIdx.x;
    const int lane = tid & 31;
    const int w    = tid >> 5;
    const int rw64 = (w >> 2) << 6;
    const int cw32 = (w & 3) << 5;
    const int lq = lane >> 2;
    const int lr = lane & 3;
    const int K = H_;

    int bx = blockIdx.x;
    int m0, cg;
    const float* A;
    if (bx < 768) { m0 = (bx / 12) << 7; cg = (bx % 12) << 7; A = x; }
    else { int t = bx - 768; m0 = (t >> 2) << 7; cg = ((t & 3) << 7) + 1536; A = pe; }
    const int seg = cg >> 9;
    const int c0  = cg & 511;
    const float* W    = (seg == 0) ? Wq : (seg == 1) ? Wk : (seg == 2) ? Wv : Wr;
    const float* bias = (seg == 0) ? bq : (seg == 1) ? bk : (seg == 2) ? bv : br;
    uint32_t* o1 = (seg == 0) ? qcP : (seg == 1) ? kP : (seg == 2) ? vP : rP;

    float C[4][4][4];
#pragma unroll
    for (int mt = 0; mt < 4; mt++)
#pragma unroll
        for (int nt = 0; nt < 4; nt++)
#pragma unroll
            for (int e = 0; e < 4; e++) C[mt][nt][e] = 0.f;

    const int arow0 = tid >> 2, aq0 = (tid & 3) << 2;
    const int arow1 = (tid + 256) >> 2, aq1 = ((tid + 256) & 3) << 2;

    auto load_chunk = [&](int st, int k0) {
        cpa16(&As[st][arow0][aq0], A + (size_t)(m0 + arow0) * K + k0 + aq0);
        cpa16(&As[st][arow1][aq1], A + (size_t)(m0 + arow1) * K + k0 + aq1);
#pragma unroll
        for (int jj = 0; jj < 2; jj++) {
            int f = tid + jj * 256;
            int kk = f >> 5, c4 = (f & 31) << 2;
            int cc = c0 + c4;
            cpa16(&Bsm[st][kk * 136 + c4],
                  W + (size_t)(cc >> 6) * ((size_t)K * 64)
                    + (size_t)(k0 + kk) * 64 + (cc & 63));
        }
    };

    const int NCH = K >> 4;
    load_chunk(0, 0);
    CPA_COMMIT();

    for (int ch = 0; ch < NCH; ch++) {
        if (ch + 1 < NCH) {
            load_chunk((ch + 1) & 1, (ch + 1) << 4);
            CPA_COMMIT();
            CPA_WAIT1();
        } else {
            CPA_WAIT0();
        }
        __syncthreads();
        const int st = ch & 1;
#pragma unroll
        for (int kc = 0; kc < 16; kc += 8) {
            uint32_t bf[4][2];
#pragma unroll
            for (int nt = 0; nt < 4; nt++) {
                int n = cw32 + 8 * nt + lq;
                bf[nt][0] = fbits(Bsm[st][(kc + lr) * 136 + n]);
                bf[nt][1] = fbits(Bsm[st][(kc + 4 + lr) * 136 + n]);
            }
#pragma unroll
            for (int mt = 0; mt < 4; mt++) {
                int i = rw64 + 16 * mt + lq;
                uint32_t a0 = fbits(As[st][i][kc + lr]);
                uint32_t a1 = fbits(As[st][i + 8][kc + lr]);
                uint32_t a2 = fbits(As[st][i][kc + 4 + lr]);
                uint32_t a3 = fbits(As[st][i + 8][kc + 4 + lr]);
#pragma unroll
                for (int nt = 0; nt < 4; nt++)
                    mma_tf32(C[mt][nt], a0, a1, a2, a3, bf[nt][0], bf[nt][1]);
            }
        }
        __syncthreads();
    }

#pragma unroll
    for (int mt = 0; mt < 4; mt++) {
        int m = m0 + rw64 + 16 * mt + lq;
#pragma unroll
        for (int nt = 0; nt < 4; nt++) {
            int c = c0 + cw32 + 8 * nt + 2 * lr;
            float b0 = bias[c], b1 = bias[c + 1];
            float v00 = C[mt][nt][0] + b0, v01 = C[mt][nt][1] + b1;
            float v10 = C[mt][nt][2] + b0, v11 = C[mt][nt][3] + b1;
            size_t w0 = (size_t)m * HW + (c >> 1), w1 = w0 + (size_t)8 * HW;
            if (seg == 0) {
                float c20 = cb[c], c21 = cb[c + 1];
                float p20 = pb[c], p21 = pb[c + 1];
                o1[w0]  = bf2(v00 + c20, v01 + c21);
                o1[w1]  = bf2(v10 + c20, v11 + c21);
                qpP[w0] = bf2(v00 + p20, v01 + p21);
                qpP[w1] = bf2(v10 + p20, v11 + p21);
            } else {
                o1[w0] = bf2(v00, v01);
                o1[w1] = bf2(v10, v11);
            }
        }
    }
}

// ---------------- bf16 GEMM for tail (Wc/W1/W2): C = A_bf16 @ W_bf16^T ----------------
// A: [M][HW] bf16 words; W: [512][HW] bf16 words; 128x128 tiles, K=512 (8 chunks of 64)
enum { GEPI_F32 = 0, GEPI_GELU_BF = 1 };
#define GB_WST 36
#define GB_STAGE 4608                 // 128*36 words
#define GB_SMEM_BYTES (4 * GB_STAGE * 4)   // A2 + B2 stages = 73728

template<int EPI>
__global__ __launch_bounds__(256, 2)
void gemm_bf16_kernel(const uint32_t* __restrict__ Ag, const uint32_t* __restrict__ Wg,
                      const float* __restrict__ bias, void* __restrict__ outv)
{
    extern __shared__ uint32_t smg[];
    const uint32_t sbase = (uint32_t)__cvta_generic_to_shared(smg);
    const int tid  = threadIdx.x;
    const int lane = tid & 31;
    const int w    = tid >> 5;
    const int lq = lane >> 2, lr = lane & 3;
    const int lt = lane >> 3, lu = lane & 7;
    const int ar = (lt & 1) * 8 + lu, ak = (lt >> 1) * 4;
    const int bn = (lt >> 1) * 8 + lu, bk = (lt & 1) * 4;
    const int m0 = blockIdx.y << 7, c0 = blockIdx.x << 7;

    float C[16][4];
#pragma unroll
    for (int nt = 0; nt < 16; nt++)
#pragma unroll
        for (int e = 0; e < 4; e++) C[nt][e] = 0.f;

    auto load_chunk = [&](int st, int ch) {
        uint32_t* sA = smg + st * GB_STAGE;
        uint32_t* sB = smg + 2 * GB_STAGE + st * GB_STAGE;
#pragma unroll
        for (int g = 0; g < 4; g++) {
            int idx = tid + 256 * g;
            int row = idx >> 3, gr = (idx & 7) << 2;
            cpa16(sA + row * GB_WST + gr, Ag + (size_t)(m0 + row) * HW + 32 * ch + gr);
            cpa16(sB + row * GB_WST + gr, Wg + (size_t)(c0 + row) * HW + 32 * ch + gr);
        }
    };

    load_chunk(0, 0);
    CPA_COMMIT();

    const int arow = (w << 4) + ar;
    for (int ch = 0; ch < 8; ch++) {
        if (ch + 1 < 8) {
            load_chunk((ch + 1) & 1, ch + 1);
            CPA_COMMIT();
            CPA_WAIT1();
        } else {
            CPA_WAIT0();
        }
        __syncthreads();
        const int st = ch & 1;
        const uint32_t sAb = sbase + (uint32_t)(st * GB_STAGE) * 4;
        const uint32_t sBb = sbase + (uint32_t)(2 * GB_STAGE + st * GB_STAGE) * 4;
#pragma unroll
        for (int k4 = 0; k4 < 4; k4++) {
            uint32_t af[4];
            ldsm4(af, sAb + (uint32_t)(arow * GB_WST + k4 * 8 + ak) * 4);
#pragma unroll
            for (int ntp = 0; ntp < 8; ntp++) {
                uint32_t bb[4];
                ldsm4(bb, sBb + (uint32_t)((16 * ntp + bn) * GB_WST + k4 * 8 + bk) * 4);
                mma_bf16(C[2 * ntp],     af[0], af[1], af[2], af[3], bb[0], bb[1]);
                mma_bf16(C[2 * ntp + 1], af[0], af[1], af[2], af[3], bb[2], bb[3]);
            }
        }
        __syncthreads();
    }

    const int ia = (w << 4) + lq, ib = ia + 8;
#pragma unroll
    for (int nt = 0; nt < 16; nt++) {
        int c = c0 + 8 * nt + 2 * lr;
        float b0 = bias[c], b1 = bias[c + 1];
        float v00 = C[nt][0] + b0, v01 = C[nt][1] + b1;
        float v10 = C[nt][2] + b0, v11 = C[nt][3] + b1;
        if (EPI == GEPI_F32) {
            float* out = (float*)outv;
            size_t o0 = (size_t)(m0 + ia) * H_ + c;
            size_t o1 = (size_t)(m0 + ib) * H_ + c;
            *(float2*)(out + o0) = make_float2(v00, v01);
            *(float2*)(out + o1) = make_float2(v10, v11);
        } else {
            v00 = v00 * 0.5f * (1.f + erff(v00 * 0.70710678118654752f));
            v01 = v01 * 0.5f * (1.f + erff(v01 * 0.70710678118654752f));
            v10 = v10 * 0.5f * (1.f + erff(v10 * 0.70710678118654752f));
            v11 = v11 * 0.5f * (1.f + erff(v11 * 0.70710678118654752f));
            uint32_t* ow = (uint32_t*)outv;
            ow[(size_t)(m0 + ia) * HW + (c >> 1)] = bf2(v00, v01);
            ow[(size_t)(m0 + ib) * HW + (c >> 1)] = bf2(v10, v11);
        }
    }
}

// ---------------- flash attention v4 (unchanged math; bf16 output) ----------------
#define WST 36
#define SPW 128
#define K_O  0
#define V_O  4608
#define R_O  9216
#define SP_O 16128
#define QC_O SP_O
#define QP_O (SP_O + 2304)
#define SM_WORDS 24320
#define ATTN_SMEM_BYTES (SM_WORDS * 4)

__global__ __launch_bounds__(256, 2)
void attn_kernel(const uint32_t* __restrict__ qcg, const uint32_t* __restrict__ qpg,
                 const uint32_t* __restrict__ kg, const uint32_t* __restrict__ vg,
                 const uint32_t* __restrict__ rg, uint32_t* __restrict__ outw)
{
    extern __shared__ uint32_t sm[];
    const uint32_t sbase = (uint32_t)__cvta_generic_to_shared(sm);
    uint16_t* sp16 = (uint16_t*)(sm + SP_O);

    const int tid  = threadIdx.x;
    const int lane = tid & 31;
    const int w    = tid >> 5;
    const bool comp = (w < 4);
    const int lq = lane >> 2, lr = lane & 3;
    const int lt = lane >> 3, lu = lane & 7;
    const int bn  = (lt >> 1) * 8 + lu;
    const int bk  = (lt & 1) * 4;
    const int vj  = (lt & 1) * 8 + lu;
    const int vd4 = (lt >> 1) * 4;
    const int ar  = (lt & 1) * 8 + lu;
    const int ak  = (lt >> 1) * 4;

    const int bh = blockIdx.y;
    const int b  = bh >> 3, n = bh & 7;
    const int i0 = ((int)gridDim.x - 1 - (int)blockIdx.x) << 6;
    const int colw = n << 5;
    const size_t rowb = (size_t)(b * L_);
    const int ni = (i0 >> 6) + 1;
    const int bl0 = 1984 - i0;

#pragma unroll
    for (int g = 0; g < 2; g++) {
        int idx = tid + 256 * g;
        int row = idx >> 3, gg = (idx & 7) << 2;
        cpa16(sm + QC_O + row * WST + gg, qcg + (rowb + i0 + row) * HW + colw + gg);
        cpa16(sm + QP_O + row * WST + gg, qpg + (rowb + i0 + row) * HW + colw + gg);
        cpa16(sm + K_O + row * WST + gg,  kg  + (rowb + row) * HW + colw + gg);
        cpa16(sm + V_O + row * WST + gg,  vg  + (rowb + row) * HW + colw + gg);
    }
#pragma unroll
    for (int g = 0; g < 6; g++) {
        int idx = tid + 256 * g;
        int row = idx >> 3, gg = (idx & 7) << 2;
        int p = bl0 + row;
        uint32_t* dst = sm + R_O + (p % 192) * WST + gg;
        if (p < L_) cpa16(dst, rg + (size_t)p * HW + colw + gg);
        else        *(uint4*)dst = make_uint4(0, 0, 0, 0);
    }
    CPA_COMMIT();
    CPA_WAIT0();
    __syncthreads();

    uint32_t aqf[4][4];
    {
        const uint32_t abase = sbase + (comp ? QC_O : QP_O) * 4;
        const int arow = ((comp ? (w & 3) : (w - 4)) << 4) + ar;
#pragma unroll
        for (int k4 = 0; k4 < 4; k4++)
            ldsm4(aqf[k4], abase + (uint32_t)(arow * WST + k4 * 8 + ak) * 4);
    }
    __syncthreads();

    const int hrow = ((w - 4) & 3) << 4;
    auto sp_block = [&](int bidx) {
        const int slotb = (bl0 + 64 * bidx) % 192;
        float SP[8][4];
#pragma unroll
        for (int nt = 0; nt < 8; nt++)
#pragma unroll
            for (int e = 0; e < 4; e++) SP[nt][e] = 0.f;
#pragma unroll
        for (int k4 = 0; k4 < 4; k4++) {
#pragma unroll
            for (int ntp = 0; ntp < 4; ntp++) {
                uint32_t bb[4];
                ldsm4(bb, sbase + (uint32_t)(R_O + (slotb + 16 * ntp + bn) * WST
                                             + k4 * 8 + bk) * 4);
                mma_bf16(SP[2 * ntp],     aqf[k4][0], aqf[k4][1], aqf[k4][2], aqf[k4][3],
                         bb[0], bb[1]);
                mma_bf16(SP[2 * ntp + 1], aqf[k4][0], aqf[k4][1], aqf[k4][2], aqf[k4][3],
                         bb[2], bb[3]);
            }
        }
        const int ja = hrow + lq, jb = ja + 8;
        const bool halo = (slotb == 0);
#pragma unroll
        for (int nt = 0; nt < 8; nt++) {
            int sw_ = (slotb + 8 * nt + 2 * lr) >> 1;
            uint32_t va = bf2(SP[nt][0], SP[nt][1]);
            uint32_t vb = bf2(SP[nt][2], SP[nt][3]);
            sm[SP_O + ja * SPW + sw_] = va;
            sm[SP_O + jb * SPW + sw_] = vb;
            if (halo) {
                sm[SP_O + ja * SPW + sw_ + 96] = va;
                sm[SP_O + jb * SPW + sw_ + 96] = vb;
            }
        }
    };

    if (!comp) { sp_block(0); sp_block(1); }

    float O[8][4];
    float l_lo = 0.f, l_hi = 0.f;
#pragma unroll
    for (int nt = 0; nt < 8; nt++)
#pragma unroll
        for (int e = 0; e < 4; e++) O[nt][e] = 0.f;
    const int ia = ((w & 3) << 4) + lq, ib = ia + 8;
    const int t2 = tid & 127;

    for (int ch = 0; ch < ni; ch++) {
        __syncthreads();
        const int j0 = ch << 6;

        if (comp) {
            const uint32_t kst = sbase + (uint32_t)(K_O + (ch & 1) * 2304) * 4;
            float S[8][4];
#pragma unroll
            for (int nt = 0; nt < 8; nt++)
#pragma unroll
                for (int e = 0; e < 4; e++) S[nt][e] = 0.f;
#pragma unroll
            for (int k4 = 0; k4 < 4; k4++) {
#pragma unroll
                for (int ntp = 0; ntp < 4; ntp++) {
                    uint32_t bb[4];
                    ldsm4(bb, kst + (uint32_t)((16 * ntp + bn) * WST + k4 * 8 + bk) * 4);
                    mma_bf16(S[2 * ntp],     aqf[k4][0], aqf[k4][1], aqf[k4][2], aqf[k4][3],
                             bb[0], bb[1]);
                    mma_bf16(S[2 * ntp + 1], aqf[k4][0], aqf[k4][1], aqf[k4][2], aqf[k4][3],
                             bb[2], bb[3]);
                }
            }
            const int pb = (1984 + j0 - i0) % 192;
            const int base_lo = pb + 63 - ia;
            const int base_hi = base_lo - 8;
            const uint16_t* srow_lo = sp16 + ia * 256;
            const uint16_t* srow_hi = sp16 + ib * 256;
            const int thr = ia + (i0 - j0);
            uint32_t pk[8][2];
#pragma unroll
            for (int nt = 0; nt < 8; nt++) {
                int jl0 = 8 * nt + 2 * lr;
                float s0 = (S[nt][0] + bfu(srow_lo[base_lo + jl0]))     * 0.125f;
                float s1 = (S[nt][1] + bfu(srow_lo[base_lo + jl0 + 1])) * 0.125f;
                float s2 = (S[nt][2] + bfu(srow_hi[base_hi + jl0]))     * 0.125f;
                float s3 = (S[nt][3] + bfu(srow_hi[base_hi + jl0 + 1])) * 0.125f;
                float p0 = (jl0     <= thr)     ? __expf(s0) : 0.f;
                float p1 = (jl0 + 1 <= thr)     ? __expf(s1) : 0.f;
                float p2 = (jl0     <= thr + 8) ? __expf(s2) : 0.f;
                float p3 = (jl0 + 1 <= thr + 8) ? __expf(s3) : 0.f;
                l_lo += p0 + p1; l_hi += p2 + p3;
                pk[nt][0] = bf2(p0, p1);
                pk[nt][1] = bf2(p2, p3);
            }
            const uint32_t vst = sbase + (uint32_t)(V_O + (ch & 1) * 2304) * 4;
#pragma unroll
            for (int t4 = 0; t4 < 4; t4++) {
                uint32_t a0 = pk[2 * t4][0], a1 = pk[2 * t4][1];
                uint32_t a2 = pk[2 * t4 + 1][0], a3 = pk[2 * t4 + 1][1];
#pragma unroll
                for (int ntp = 0; ntp < 4; ntp++) {
                    uint32_t bb[4];
                    ldsm4t(bb, vst + (uint32_t)((t4 * 16 + vj) * WST + 8 * ntp + vd4) * 4);
                    mma_bf16(O[2 * ntp],     a0, a1, a2, a3, bb[0], bb[1]);
                    mma_bf16(O[2 * ntp + 1], a0, a1, a2, a3, bb[2], bb[3]);
                }
            }
        } else {
            if (ch + 2 <= ni) sp_block(ch + 2);
            if (ch + 1 < ni) {
#pragma unroll
                for (int g = 0; g < 4; g++) {
                    int idx = t2 + 128 * g;
                    int row = idx >> 3, gg = (idx & 7) << 2;
                    cpa16(sm + K_O + ((ch + 1) & 1) * 2304 + row * WST + gg,
                          kg + (rowb + j0 + 64 + row) * HW + colw + gg);
                    cpa16(sm + V_O + ((ch + 1) & 1) * 2304 + row * WST + gg,
                          vg + (rowb + j0 + 64 + row) * HW + colw + gg);
                }
                if (ch + 3 <= ni) {
#pragma unroll
                    for (int g = 0; g < 4; g++) {
                        int idx = t2 + 128 * g;
                        int row = idx >> 3, gg = (idx & 7) << 2;
                        int p = bl0 + 64 * (ch + 3) + row;
                        uint32_t* dst = sm + R_O + (p % 192) * WST + gg;
                        if (p < L_) cpa16(dst, rg + (size_t)p * HW + colw + gg);
                        else        *(uint4*)dst = make_uint4(0, 0, 0, 0);
                    }
                }
                CPA_COMMIT();
                CPA_WAIT0();
            }
        }
    }

    if (comp) {
        l_lo += __shfl_xor_sync(0xffffffffu, l_lo, 1);
        l_lo += __shfl_xor_sync(0xffffffffu, l_lo, 2);
        l_hi += __shfl_xor_sync(0xffffffffu, l_hi, 1);
        l_hi += __shfl_xor_sync(0xffffffffu, l_hi, 2);
        float la = 1.f / l_lo, lb = 1.f / l_hi;
        const size_t obase = (rowb + i0) * HW + colw;
#pragma unroll
        for (int nt = 0; nt < 8; nt++) {
            outw[obase + (size_t)ia * HW + 4 * nt + lr] =
                bf2(O[nt][0] * la, O[nt][1] * la);
            outw[obase + (size_t)ib * HW + 4 * nt + lr] =
                bf2(O[nt][2] * lb, O[nt][3] * lb);
        }
    }
}

// ---------------- fused residual-add + LayerNorm (float2 lanes, optional bf16 aux) ----------------
__global__ __launch_bounds__(256)
void ln_kernel(const float* __restrict__ a, const float* __restrict__ b,
               const float* __restrict__ w, const float* __restrict__ beta,
               float* __restrict__ out, uint32_t* __restrict__ auxbf)
{
    const int row = blockIdx.x;
    const int tid = threadIdx.x;
    const int col = 2 * tid;
    const size_t base = (size_t)row * H_;
    float2 av = *(const float2*)(a + base + col);
    float2 bv = *(const float2*)(b + base + col);
    float x0 = av.x + bv.x;
    float x1 = av.y + bv.y;
    float s  = x0 + x1;
    float sq = x0 * x0 + x1 * x1;
#pragma unroll
    for (int o = 16; o > 0; o >>= 1) {
        s  += __shfl_xor_sync(0xffffffffu, s,  o);
        sq += __shfl_xor_sync(0xffffffffu, sq, o);
    }
    __shared__ float rs[8], rq[8];
    int wid = tid >> 5;
    if ((tid & 31) == 0) { rs[wid] = s; rq[wid] = sq; }
    __syncthreads();
    if (tid < 32) {
        float ss = (tid < 8) ? rs[tid] : 0.f;
        float qq = (tid < 8) ? rq[tid] : 0.f;
#pragma unroll
        for (int o = 4; o > 0; o >>= 1) {
            ss += __shfl_xor_sync(0xffffffffu, ss, o);
            qq += __shfl_xor_sync(0xffffffffu, qq, o);
        }
        if (tid == 0) { rs[0] = ss; rq[0] = qq; }
    }
    __syncthreads();
    float mean = rs[0] * (1.f / H_);
    float var  = rq[0] * (1.f / H_) - mean * mean;
    float inv  = rsqrtf(var + 1e-12f);
    float y0 = w[col]     * (x0 - mean) * inv + beta[col];
    float y1 = w[col + 1] * (x1 - mean) * inv + beta[col + 1];
    *(float2*)(out + base + col) = make_float2(y0, y1);
    if (auxbf) auxbf[(size_t)row * HW + tid] = bf2(y0, y1);
}

// ---------------- launcher ----------------
extern "C" void kernel_launch(void* const* d_in, const int* in_sizes, int n_in,
                              void* d_out, int out_size)
{
    const float* x   = (const float*)d_in[0];
    const float* pe  = (const float*)d_in[1];
    const float* Wq  = (const float*)d_in[2];
    const float* bq  = (const float*)d_in[3];
    const float* Wk  = (const float*)d_in[4];
    const float* bk  = (const float*)d_in[5];
    const float* Wv  = (const float*)d_in[6];
    const float* bv  = (const float*)d_in[7];
    const float* Wr  = (const float*)d_in[8];
    const float* br  = (const float*)d_in[9];
    const float* cb  = (const float*)d_in[10];
    const float* pb  = (const float*)d_in[11];
    const float* Wc  = (const float*)d_in[12];
    const float* bc  = (const float*)d_in[13];
    const float* W1  = (const float*)d_in[14];
    const float* b1  = (const float*)d_in[15];
    const float* W2  = (const float*)d_in[16];
    const float* b2  = (const float*)d_in[17];
    const float* lnw = (const float*)d_in[18];
    const float* lnb = (const float*)d_in[19];
    float* out = (float*)d_out;

    uint32_t *qcP, *qpP, *kP, *vP, *rP, *wcbP, *w1bP, *w2bP;
    float *attnP, *t1P, *aP, *h2P;
    cudaGetSymbolAddress((void**)&qcP,   g_qc);
    cudaGetSymbolAddress((void**)&qpP,   g_qp);
    cudaGetSymbolAddress((void**)&kP,    g_k);
    cudaGetSymbolAddress((void**)&vP,    g_v);
    cudaGetSymbolAddress((void**)&rP,    g_r);
    cudaGetSymbolAddress((void**)&attnP, g_attn);
    cudaGetSymbolAddress((void**)&t1P,   g_t1);
    cudaGetSymbolAddress((void**)&aP,    g_a);
    cudaGetSymbolAddress((void**)&h2P,   g_h2);
    cudaGetSymbolAddress((void**)&wcbP,  g_wcb);
    cudaGetSymbolAddress((void**)&w1bP,  g_w1b);
    cudaGetSymbolAddress((void**)&w2bP,  g_w2b);
    uint32_t* attw = (uint32_t*)attnP;

    const dim3 gBig(H_ / 128, M_ / 128);   // (4, 64)

    cvt_w_kernel<<<512, 256>>>(Wc, W1, W2, wcbP, w1bP, w2bP);
    proj_kernel<<<832, 256>>>(x, pe, Wq, bq, cb, pb, Wk, bk, Wv, bv, Wr, br,
                              qcP, qpP, kP, vP, rP);

    cudaFuncSetAttribute(attn_kernel, cudaFuncAttributeMaxDynamicSharedMemorySize, ATTN_SMEM_BYTES);
    attn_kernel<<<dim3(L_ / 64, B_ * N_), 256, ATTN_SMEM_BYTES>>>(qcP, qpP, kP, vP, rP, attw);

    cudaFuncSetAttribute(gemm_bf16_kernel<GEPI_F32>,
                         cudaFuncAttributeMaxDynamicSharedMemorySize, GB_SMEM_BYTES);
    cudaFuncSetAttribute(gemm_bf16_kernel<GEPI_GELU_BF>,
                         cudaFuncAttributeMaxDynamicSharedMemorySize, GB_SMEM_BYTES);

    gemm_bf16_kernel<GEPI_F32><<<gBig, 256, GB_SMEM_BYTES>>>(attw, wcbP, bc, t1P);
    ln_kernel<<<M_, 256>>>(t1P, x, lnw, lnb, aP, qcP);   // qcP reused as bf16 aux

    gemm_bf16_kernel<GEPI_GELU_BF><<<gBig, 256, GB_SMEM_BYTES>>>(qcP, w1bP, b1, kP);  // kP = h1 bf16
    gemm_bf16_kernel<GEPI_F32><<<gBig, 256, GB_SMEM_BYTES>>>(kP, w2bP, b2, h2P);
    ln_kernel<<<M_, 256>>>(aP, h2P, lnw, lnb, out, nullptr);
}

// round 17
// speedup vs baseline: 1.2497x; 1.0798x over previous
#include <cuda_runtime.h>
#include <cuda_bf16.h>
#include <math.h>
#include <stdint.h>

#define B_  4
#define L_  2048
#define H_  512
#define N_  8
#define D_  64
#define M_  (B_*L_)   // 8192 rows
#define HW  256       // H_/2 words per row (bf16x2)

// ---------------- scratch ----------------
__device__ uint32_t g_qc[M_*HW];   // bf16x2 (reused as LN1 bf16 aux)
__device__ uint32_t g_qp[M_*HW];
__device__ uint32_t g_k [M_*HW];   // reused as h1 bf16
__device__ uint32_t g_v [M_*HW];
__device__ uint32_t g_r [L_*HW];
__device__ uint32_t g_xb[M_*HW];   // x in bf16
__device__ uint32_t g_peb[L_*HW];  // pe in bf16
__device__ uint32_t g_wqkvr[2048*HW];  // packed proj weights bf16 [globalcol][k]
__device__ float g_attn[M_*H_];
__device__ float g_t1  [M_*H_];
__device__ float g_a   [M_*H_];
__device__ float g_h2  [M_*H_];
__device__ uint32_t g_wcb[H_*HW];
__device__ uint32_t g_w1b[H_*HW];
__device__ uint32_t g_w2b[H_*HW];

// ---------------- helpers ----------------
__device__ __forceinline__ uint32_t bf2(float x, float y) {
    __nv_bfloat162 t = __floats2bfloat162_rn(x, y);
    return *(uint32_t*)&t;
}
__device__ __forceinline__ float bfu(uint16_t h) {
    return __uint_as_float(((uint32_t)h) << 16);
}
__device__ __forceinline__ void cpa16(void* dst, const void* src) {
    uint32_t d = (uint32_t)__cvta_generic_to_shared(dst);
    asm volatile("cp.async.ca.shared.global [%0], [%1], 16;" :: "r"(d), "l"(src));
}
#define CPA_COMMIT() asm volatile("cp.async.commit_group;")
#define CPA_WAIT1()  asm volatile("cp.async.wait_group 1;")
#define CPA_WAIT0()  asm volatile("cp.async.wait_group 0;")

__device__ __forceinline__ void mma_bf16(float* c,
                                         uint32_t a0, uint32_t a1, uint32_t a2, uint32_t a3,
                                         uint32_t b0, uint32_t b1) {
    asm("mma.sync.aligned.m16n8k16.row.col.f32.bf16.bf16.f32 "
        "{%0,%1,%2,%3}, {%4,%5,%6,%7}, {%8,%9}, {%0,%1,%2,%3};"
        : "+f"(c[0]), "+f"(c[1]), "+f"(c[2]), "+f"(c[3])
        : "r"(a0), "r"(a1), "r"(a2), "r"(a3), "r"(b0), "r"(b1));
}
__device__ __forceinline__ void ldsm4(uint32_t* r, uint32_t a) {
    asm volatile("ldmatrix.sync.aligned.m8n8.x4.shared.b16 {%0,%1,%2,%3}, [%4];"
        : "=r"(r[0]), "=r"(r[1]), "=r"(r[2]), "=r"(r[3]) : "r"(a));
}
__device__ __forceinline__ void ldsm4t(uint32_t* r, uint32_t a) {
    asm volatile("ldmatrix.sync.aligned.m8n8.x4.trans.shared.b16 {%0,%1,%2,%3}, [%4];"
        : "=r"(r[0]), "=r"(r[1]), "=r"(r[2]), "=r"(r[3]) : "r"(a));
}

// ---------------- conversion kernels ----------------
__global__ __launch_bounds__(256)
void cvt_w_kernel(const float* __restrict__ Wc, const float* __restrict__ W1,
                  const float* __restrict__ W2,
                  uint32_t* __restrict__ wcb, uint32_t* __restrict__ w1b,
                  uint32_t* __restrict__ w2b)
{
    int i = blockIdx.x * 256 + threadIdx.x;
    float2 a = *(const float2*)(Wc + 2 * i);
    float2 b = *(const float2*)(W1 + 2 * i);
    float2 c = *(const float2*)(W2 + 2 * i);
    wcb[i] = bf2(a.x, a.y);
    w1b[i] = bf2(b.x, b.y);
    w2b[i] = bf2(c.x, c.y);
}

__global__ __launch_bounds__(256)
void cvt_x_kernel(const float* __restrict__ x, const float* __restrict__ pe,
                  uint32_t* __restrict__ xb, uint32_t* __restrict__ peb)
{
    int i = blockIdx.x * 256 + threadIdx.x;   // < M_*HW + L_*HW
    if (i < M_ * HW) {
        float2 a = *(const float2*)(x + 2 * (size_t)i);
        xb[i] = bf2(a.x, a.y);
    } else {
        int j = i - M_ * HW;
        float2 a = *(const float2*)(pe + 2 * (size_t)j);
        peb[j] = bf2(a.x, a.y);
    }
}

// gather NHD weights -> flat [globalcol][k] bf16
__global__ __launch_bounds__(256)
void cvt_wqkvr_kernel(const float* __restrict__ Wq, const float* __restrict__ Wk,
                      const float* __restrict__ Wv, const float* __restrict__ Wr,
                      uint32_t* __restrict__ wall)
{
    int i = blockIdx.x * 256 + threadIdx.x;   // < 2048*256
    int cc = i >> 8, kw = i & 255;
    int seg = cc >> 9, c = cc & 511;
    int n = c >> 6, d = c & 63;
    const float* W = (seg == 0) ? Wq : (seg == 1) ? Wk : (seg == 2) ? Wv : Wr;
    float v0 = W[(size_t)n * (512 * 64) + (size_t)(2 * kw) * 64 + d];
    float v1 = W[(size_t)n * (512 * 64) + (size_t)(2 * kw + 1) * 64 + d];
    wall[i] = bf2(v0, v1);
}

// ---------------- bf16 GEMM core (tail + projections) ----------------
enum { GEPI_F32 = 0, GEPI_GELU_BF = 1 };
#define GB_WST 36
#define GB_STAGE 4608
#define GB_SMEM_BYTES (4 * GB_STAGE * 4)   // 73728

template<int EPI>
__global__ __launch_bounds__(256, 2)
void gemm_bf16_kernel(const uint32_t* __restrict__ Ag, const uint32_t* __restrict__ Wg,
                      const float* __restrict__ bias, void* __restrict__ outv)
{
    extern __shared__ uint32_t smg[];
    const uint32_t sbase = (uint32_t)__cvta_generic_to_shared(smg);
    const int tid  = threadIdx.x;
    const int lane = tid & 31;
    const int w    = tid >> 5;
    const int lq = lane >> 2, lr = lane & 3;
    const int lt = lane >> 3, lu = lane & 7;
    const int ar = (lt & 1) * 8 + lu, ak = (lt >> 1) * 4;
    const int bn = (lt >> 1) * 8 + lu, bk = (lt & 1) * 4;
    const int m0 = blockIdx.y << 7, c0 = blockIdx.x << 7;

    float C[16][4];
#pragma unroll
    for (int nt = 0; nt < 16; nt++)
#pragma unroll
        for (int e = 0; e < 4; e++) C[nt][e] = 0.f;

    auto load_chunk = [&](int st, int ch) {
        uint32_t* sA = smg + st * GB_STAGE;
        uint32_t* sB = smg + 2 * GB_STAGE + st * GB_STAGE;
#pragma unroll
        for (int g = 0; g < 4; g++) {
            int idx = tid + 256 * g;
            int row = idx >> 3, gr = (idx & 7) << 2;
            cpa16(sA + row * GB_WST + gr, Ag + (size_t)(m0 + row) * HW + 32 * ch + gr);
            cpa16(sB + row * GB_WST + gr, Wg + (size_t)(c0 + row) * HW + 32 * ch + gr);
        }
    };

    load_chunk(0, 0);
    CPA_COMMIT();

    const int arow = (w << 4) + ar;
    for (int ch = 0; ch < 8; ch++) {
        if (ch + 1 < 8) {
            load_chunk((ch + 1) & 1, ch + 1);
            CPA_COMMIT();
            CPA_WAIT1();
        } else {
            CPA_WAIT0();
        }
        __syncthreads();
        const int st = ch & 1;
        const uint32_t sAb = sbase + (uint32_t)(st * GB_STAGE) * 4;
        const uint32_t sBb = sbase + (uint32_t)(2 * GB_STAGE + st * GB_STAGE) * 4;
#pragma unroll
        for (int k4 = 0; k4 < 4; k4++) {
            uint32_t af[4];
            ldsm4(af, sAb + (uint32_t)(arow * GB_WST + k4 * 8 + ak) * 4);
#pragma unroll
            for (int ntp = 0; ntp < 8; ntp++) {
                uint32_t bb[4];
                ldsm4(bb, sBb + (uint32_t)((16 * ntp + bn) * GB_WST + k4 * 8 + bk) * 4);
                mma_bf16(C[2 * ntp],     af[0], af[1], af[2], af[3], bb[0], bb[1]);
                mma_bf16(C[2 * ntp + 1], af[0], af[1], af[2], af[3], bb[2], bb[3]);
            }
        }
        __syncthreads();
    }

    const int ia = (w << 4) + lq, ib = ia + 8;
#pragma unroll
    for (int nt = 0; nt < 16; nt++) {
        int c = c0 + 8 * nt + 2 * lr;
        float b0 = bias[c], b1 = bias[c + 1];
        float v00 = C[nt][0] + b0, v01 = C[nt][1] + b1;
        float v10 = C[nt][2] + b0, v11 = C[nt][3] + b1;
        if (EPI == GEPI_F32) {
            float* out = (float*)outv;
            *(float2*)(out + (size_t)(m0 + ia) * H_ + c) = make_float2(v00, v01);
            *(float2*)(out + (size_t)(m0 + ib) * H_ + c) = make_float2(v10, v11);
        } else {
            v00 = v00 * 0.5f * (1.f + erff(v00 * 0.70710678118654752f));
            v01 = v01 * 0.5f * (1.f + erff(v01 * 0.70710678118654752f));
            v10 = v10 * 0.5f * (1.f + erff(v10 * 0.70710678118654752f));
            v11 = v11 * 0.5f * (1.f + erff(v11 * 0.70710678118654752f));
            uint32_t* ow = (uint32_t*)outv;
            ow[(size_t)(m0 + ia) * HW + (c >> 1)] = bf2(v00, v01);
            ow[(size_t)(m0 + ib) * HW + (c >> 1)] = bf2(v10, v11);
        }
    }
}

// ---------------- bf16 projection GEMM (QKV from x, R from pe) ----------------
__global__ __launch_bounds__(256, 2)
void projb_kernel(const uint32_t* __restrict__ xb, const uint32_t* __restrict__ peb,
                  const uint32_t* __restrict__ wall,
                  const float* __restrict__ bq, const float* __restrict__ bk_,
                  const float* __restrict__ bv, const float* __restrict__ br,
                  const float* __restrict__ cb, const float* __restrict__ pb,
                  uint32_t* __restrict__ qcP, uint32_t* __restrict__ qpP,
                  uint32_t* __restrict__ kP, uint32_t* __restrict__ vP,
                  uint32_t* __restrict__ rP)
{
    extern __shared__ uint32_t smg[];
    const uint32_t sbase = (uint32_t)__cvta_generic_to_shared(smg);
    const int tid  = threadIdx.x;
    const int lane = tid & 31;
    const int w    = tid >> 5;
    const int lq = lane >> 2, lr = lane & 3;
    const int lt = lane >> 3, lu = lane & 7;
    const int ar = (lt & 1) * 8 + lu, ak = (lt >> 1) * 4;
    const int bn = (lt >> 1) * 8 + lu, bk = (lt & 1) * 4;

    int bx = blockIdx.x;
    int m0, cg;
    const uint32_t* A;
    if (bx < 768) { m0 = (bx / 12) << 7; cg = (bx % 12) << 7; A = xb; }
    else { int t = bx - 768; m0 = (t >> 2) << 7; cg = ((t & 3) << 7) + 1536; A = peb; }
    const int seg = cg >> 9;
    const int cs0 = cg & 511;
    const float* bias = (seg == 0) ? bq : (seg == 1) ? bk_ : (seg == 2) ? bv : br;
    uint32_t* o1 = (seg == 0) ? qcP : (seg == 1) ? kP : (seg == 2) ? vP : rP;

    float C[16][4];
#pragma unroll
    for (int nt = 0; nt < 16; nt++)
#pragma unroll
        for (int e = 0; e < 4; e++) C[nt][e] = 0.f;

    auto load_chunk = [&](int st, int ch) {
        uint32_t* sA = smg + st * GB_STAGE;
        uint32_t* sB = smg + 2 * GB_STAGE + st * GB_STAGE;
#pragma unroll
        for (int g = 0; g < 4; g++) {
            int idx = tid + 256 * g;
            int row = idx >> 3, gr = (idx & 7) << 2;
            cpa16(sA + row * GB_WST + gr, A + (size_t)(m0 + row) * HW + 32 * ch + gr);
            cpa16(sB + row * GB_WST + gr, wall + (size_t)(cg + row) * HW + 32 * ch + gr);
        }
    };

    load_chunk(0, 0);
    CPA_COMMIT();

    const int arow = (w << 4) + ar;
    for (int ch = 0; ch < 8; ch++) {
        if (ch + 1 < 8) {
            load_chunk((ch + 1) & 1, ch + 1);
            CPA_COMMIT();
            CPA_WAIT1();
        } else {
            CPA_WAIT0();
        }
        __syncthreads();
        const int st = ch & 1;
        const uint32_t sAb = sbase + (uint32_t)(st * GB_STAGE) * 4;
        const uint32_t sBb = sbase + (uint32_t)(2 * GB_STAGE + st * GB_STAGE) * 4;
#pragma unroll
        for (int k4 = 0; k4 < 4; k4++) {
            uint32_t af[4];
            ldsm4(af, sAb + (uint32_t)(arow * GB_WST + k4 * 8 + ak) * 4);
#pragma unroll
            for (int ntp = 0; ntp < 8; ntp++) {
                uint32_t bb[4];
                ldsm4(bb, sBb + (uint32_t)((16 * ntp + bn) * GB_WST + k4 * 8 + bk) * 4);
                mma_bf16(C[2 * ntp],     af[0], af[1], af[2], af[3], bb[0], bb[1]);
                mma_bf16(C[2 * ntp + 1], af[0], af[1], af[2], af[3], bb[2], bb[3]);
            }
        }
        __syncthreads();
    }

    const int ia = (w << 4) + lq, ib = ia + 8;
#pragma unroll
    for (int nt = 0; nt < 16; nt++) {
        int c = cs0 + 8 * nt + 2 * lr;
        float b0 = bias[c], b1 = bias[c + 1];
        float v00 = C[nt][0] + b0, v01 = C[nt][1] + b1;
        float v10 = C[nt][2] + b0, v11 = C[nt][3] + b1;
        size_t w0 = (size_t)(m0 + ia) * HW + (c >> 1);
        size_t w1 = (size_t)(m0 + ib) * HW + (c >> 1);
        if (seg == 0) {
            float c20 = cb[c], c21 = cb[c + 1];
            float p20 = pb[c], p21 = pb[c + 1];
            o1[w0]  = bf2(v00 + c20, v01 + c21);
            o1[w1]  = bf2(v10 + c20, v11 + c21);
            qpP[w0] = bf2(v00 + p20, v01 + p21);
            qpP[w1] = bf2(v10 + p20, v11 + p21);
        } else {
            o1[w0] = bf2(v00, v01);
            o1[w1] = bf2(v10, v11);
        }
    }
}

// ---------------- flash attention v4 (unchanged) ----------------
#define WST 36
#define SPW 128
#define K_O  0
#define V_O  4608
#define R_O  9216
#define SP_O 16128
#define QC_O SP_O
#define QP_O (SP_O + 2304)
#define SM_WORDS 24320
#define ATTN_SMEM_BYTES (SM_WORDS * 4)

__global__ __launch_bounds__(256, 2)
void attn_kernel(const uint32_t* __restrict__ qcg, const uint32_t* __restrict__ qpg,
                 const uint32_t* __restrict__ kg, const uint32_t* __restrict__ vg,
                 const uint32_t* __restrict__ rg, uint32_t* __restrict__ outw)
{
    extern __shared__ uint32_t sm[];
    const uint32_t sbase = (uint32_t)__cvta_generic_to_shared(sm);
    uint16_t* sp16 = (uint16_t*)(sm + SP_O);

    const int tid  = threadIdx.x;
    const int lane = tid & 31;
    const int w    = tid >> 5;
    const bool comp = (w < 4);
    const int lq = lane >> 2, lr = lane & 3;
    const int lt = lane >> 3, lu = lane & 7;
    const int bn  = (lt >> 1) * 8 + lu;
    const int bk  = (lt & 1) * 4;
    const int vj  = (lt & 1) * 8 + lu;
    const int vd4 = (lt >> 1) * 4;
    const int ar  = (lt & 1) * 8 + lu;
    const int ak  = (lt >> 1) * 4;

    const int bh = blockIdx.y;
    const int b  = bh >> 3, n = bh & 7;
    const int i0 = ((int)gridDim.x - 1 - (int)blockIdx.x) << 6;
    const int colw = n << 5;
    const size_t rowb = (size_t)(b * L_);
    const int ni = (i0 >> 6) + 1;
    const int bl0 = 1984 - i0;

#pragma unroll
    for (int g = 0; g < 2; g++) {
        int idx = tid + 256 * g;
        int row = idx >> 3, gg = (idx & 7) << 2;
        cpa16(sm + QC_O + row * WST + gg, qcg + (rowb + i0 + row) * HW + colw + gg);
        cpa16(sm + QP_O + row * WST + gg, qpg + (rowb + i0 + row) * HW + colw + gg);
        cpa16(sm + K_O + row * WST + gg,  kg  + (rowb + row) * HW + colw + gg);
        cpa16(sm + V_O + row * WST + gg,  vg  + (rowb + row) * HW + colw + gg);
    }
#pragma unroll
    for (int g = 0; g < 6; g++) {
        int idx = tid + 256 * g;
        int row = idx >> 3, gg = (idx & 7) << 2;
        int p = bl0 + row;
        uint32_t* dst = sm + R_O + (p % 192) * WST + gg;
        if (p < L_) cpa16(dst, rg + (size_t)p * HW + colw + gg);
        else        *(uint4*)dst = make_uint4(0, 0, 0, 0);
    }
    CPA_COMMIT();
    CPA_WAIT0();
    __syncthreads();

    uint32_t aqf[4][4];
    {
        const uint32_t abase = sbase + (comp ? QC_O : QP_O) * 4;
        const int arow = ((comp ? (w & 3) : (w - 4)) << 4) + ar;
#pragma unroll
        for (int k4 = 0; k4 < 4; k4++)
            ldsm4(aqf[k4], abase + (uint32_t)(arow * WST + k4 * 8 + ak) * 4);
    }
    __syncthreads();

    const int hrow = ((w - 4) & 3) << 4;
    auto sp_block = [&](int bidx) {
        const int slotb = (bl0 + 64 * bidx) % 192;
        float SP[8][4];
#pragma unroll
        for (int nt = 0; nt < 8; nt++)
#pragma unroll
            for (int e = 0; e < 4; e++) SP[nt][e] = 0.f;
#pragma unroll
        for (int k4 = 0; k4 < 4; k4++) {
#pragma unroll
            for (int ntp = 0; ntp < 4; ntp++) {
                uint32_t bb[4];
                ldsm4(bb, sbase + (uint32_t)(R_O + (slotb + 16 * ntp + bn) * WST
                                             + k4 * 8 + bk) * 4);
                mma_bf16(SP[2 * ntp],     aqf[k4][0], aqf[k4][1], aqf[k4][2], aqf[k4][3],
                         bb[0], bb[1]);
                mma_bf16(SP[2 * ntp + 1], aqf[k4][0], aqf[k4][1], aqf[k4][2], aqf[k4][3],
                         bb[2], bb[3]);
            }
        }
        const int ja = hrow + lq, jb = ja + 8;
        const bool halo = (slotb == 0);
#pragma unroll
        for (int nt = 0; nt < 8; nt++) {
            int sw_ = (slotb + 8 * nt + 2 * lr) >> 1;
            uint32_t va = bf2(SP[nt][0], SP[nt][1]);
            uint32_t vb = bf2(SP[nt][2], SP[nt][3]);
            sm[SP_O + ja * SPW + sw_] = va;
            sm[SP_O + jb * SPW + sw_] = vb;
            if (halo) {
                sm[SP_O + ja * SPW + sw_ + 96] = va;
                sm[SP_O + jb * SPW + sw_ + 96] = vb;
            }
        }
    };

    if (!comp) { sp_block(0); sp_block(1); }

    float O[8][4];
    float l_lo = 0.f, l_hi = 0.f;
#pragma unroll
    for (int nt = 0; nt < 8; nt++)
#pragma unroll
        for (int e = 0; e < 4; e++) O[nt][e] = 0.f;
    const int ia = ((w & 3) << 4) + lq, ib = ia + 8;
    const int t2 = tid & 127;

    for (int ch = 0; ch < ni; ch++) {
        __syncthreads();
        const int j0 = ch << 6;

        if (comp) {
            const uint32_t kst = sbase + (uint32_t)(K_O + (ch & 1) * 2304) * 4;
            float S[8][4];
#pragma unroll
            for (int nt = 0; nt < 8; nt++)
#pragma unroll
                for (int e = 0; e < 4; e++) S[nt][e] = 0.f;
#pragma unroll
            for (int k4 = 0; k4 < 4; k4++) {
#pragma unroll
                for (int ntp = 0; ntp < 4; ntp++) {
                    uint32_t bb[4];
                    ldsm4(bb, kst + (uint32_t)((16 * ntp + bn) * WST + k4 * 8 + bk) * 4);
                    mma_bf16(S[2 * ntp],     aqf[k4][0], aqf[k4][1], aqf[k4][2], aqf[k4][3],
                             bb[0], bb[1]);
                    mma_bf16(S[2 * ntp + 1], aqf[k4][0], aqf[k4][1], aqf[k4][2], aqf[k4][3],
                             bb[2], bb[3]);
                }
            }
            const int pb = (1984 + j0 - i0) % 192;
            const int base_lo = pb + 63 - ia;
            const int base_hi = base_lo - 8;
            const uint16_t* srow_lo = sp16 + ia * 256;
            const uint16_t* srow_hi = sp16 + ib * 256;
            const int thr = ia + (i0 - j0);
            uint32_t pk[8][2];
#pragma unroll
            for (int nt = 0; nt < 8; nt++) {
                int jl0 = 8 * nt + 2 * lr;
                float s0 = (S[nt][0] + bfu(srow_lo[base_lo + jl0]))     * 0.125f;
                float s1 = (S[nt][1] + bfu(srow_lo[base_lo + jl0 + 1])) * 0.125f;
                float s2 = (S[nt][2] + bfu(srow_hi[base_hi + jl0]))     * 0.125f;
                float s3 = (S[nt][3] + bfu(srow_hi[base_hi + jl0 + 1])) * 0.125f;
                float p0 = (jl0     <= thr)     ? __expf(s0) : 0.f;
                float p1 = (jl0 + 1 <= thr)     ? __expf(s1) : 0.f;
                float p2 = (jl0     <= thr + 8) ? __expf(s2) : 0.f;
                float p3 = (jl0 + 1 <= thr + 8) ? __expf(s3) : 0.f;
                l_lo += p0 + p1; l_hi += p2 + p3;
                pk[nt][0] = bf2(p0, p1);
                pk[nt][1] = bf2(p2, p3);
            }
            const uint32_t vst = sbase + (uint32_t)(V_O + (ch & 1) * 2304) * 4;
#pragma unroll
            for (int t4 = 0; t4 < 4; t4++) {
                uint32_t a0 = pk[2 * t4][0], a1 = pk[2 * t4][1];
                uint32_t a2 = pk[2 * t4 + 1][0], a3 = pk[2 * t4 + 1][1];
#pragma unroll
                for (int ntp = 0; ntp < 4; ntp++) {
                    uint32_t bb[4];
                    ldsm4t(bb, vst + (uint32_t)((t4 * 16 + vj) * WST + 8 * ntp + vd4) * 4);
                    mma_bf16(O[2 * ntp],     a0, a1, a2, a3, bb[0], bb[1]);
                    mma_bf16(O[2 * ntp + 1], a0, a1, a2, a3, bb[2], bb[3]);
                }
            }
        } else {
            if (ch + 2 <= ni) sp_block(ch + 2);
            if (ch + 1 < ni) {
#pragma unroll
                for (int g = 0; g < 4; g++) {
                    int idx = t2 + 128 * g;
                    int row = idx >> 3, gg = (idx & 7) << 2;
                    cpa16(sm + K_O + ((ch + 1) & 1) * 2304 + row * WST + gg,
                          kg + (rowb + j0 + 64 + row) * HW + colw + gg);
                    cpa16(sm + V_O + ((ch + 1) & 1) * 2304 + row * WST + gg,
                          vg + (rowb + j0 + 64 + row) * HW + colw + gg);
                }
                if (ch + 3 <= ni) {
#pragma unroll
                    for (int g = 0; g < 4; g++) {
                        int idx = t2 + 128 * g;
                        int row = idx >> 3, gg = (idx & 7) << 2;
                        int p = bl0 + 64 * (ch + 3) + row;
                        uint32_t* dst = sm + R_O + (p % 192) * WST + gg;
                        if (p < L_) cpa16(dst, rg + (size_t)p * HW + colw + gg);
                        else        *(uint4*)dst = make_uint4(0, 0, 0, 0);
                    }
                }
                CPA_COMMIT();
                CPA_WAIT0();
            }
        }
    }

    if (comp) {
        l_lo += __shfl_xor_sync(0xffffffffu, l_lo, 1);
        l_lo += __shfl_xor_sync(0xffffffffu, l_lo, 2);
        l_hi += __shfl_xor_sync(0xffffffffu, l_hi, 1);
        l_hi += __shfl_xor_sync(0xffffffffu, l_hi, 2);
        float la = 1.f / l_lo, lb = 1.f / l_hi;
        const size_t obase = (rowb + i0) * HW + colw;
#pragma unroll
        for (int nt = 0; nt < 8; nt++) {
            outw[obase + (size_t)ia * HW + 4 * nt + lr] =
                bf2(O[nt][0] * la, O[nt][1] * la);
            outw[obase + (size_t)ib * HW + 4 * nt + lr] =
                bf2(O[nt][2] * lb, O[nt][3] * lb);
        }
    }
}

// ---------------- fused residual-add + LayerNorm ----------------
__global__ __launch_bounds__(256)
void ln_kernel(const float* __restrict__ a, const float* __restrict__ b,
               const float* __restrict__ w, const float* __restrict__ beta,
               float* __restrict__ out, uint32_t* __restrict__ auxbf)
{
    const int row = blockIdx.x;
    const int tid = threadIdx.x;
    const int col = 2 * tid;
    const size_t base = (size_t)row * H_;
    float2 av = *(const float2*)(a + base + col);
    float2 bv = *(const float2*)(b + base + col);
    float x0 = av.x + bv.x;
    float x1 = av.y + bv.y;
    float s  = x0 + x1;
    float sq = x0 * x0 + x1 * x1;
#pragma unroll
    for (int o = 16; o > 0; o >>= 1) {
        s  += __shfl_xor_sync(0xffffffffu, s,  o);
        sq += __shfl_xor_sync(0xffffffffu, sq, o);
    }
    __shared__ float rs[8], rq[8];
    int wid = tid >> 5;
    if ((tid & 31) == 0) { rs[wid] = s; rq[wid] = sq; }
    __syncthreads();
    if (tid < 32) {
        float ss = (tid < 8) ? rs[tid] : 0.f;
        float qq = (tid < 8) ? rq[tid] : 0.f;
#pragma unroll
        for (int o = 4; o > 0; o >>= 1) {
            ss += __shfl_xor_sync(0xffffffffu, ss, o);
            qq += __shfl_xor_sync(0xffffffffu, qq, o);
        }
        if (tid == 0) { rs[0] = ss; rq[0] = qq; }
    }
    __syncthreads();
    float mean = rs[0] * (1.f / H_);
    float var  = rq[0] * (1.f / H_) - mean * mean;
    float inv  = rsqrtf(var + 1e-12f);
    float y0 = w[col]     * (x0 - mean) * inv + beta[col];
    float y1 = w[col + 1] * (x1 - mean) * inv + beta[col + 1];
    *(float2*)(out + base + col) = make_float2(y0, y1);
    if (auxbf) auxbf[(size_t)row * HW + tid] = bf2(y0, y1);
}

// ---------------- launcher ----------------
extern "C" void kernel_launch(void* const* d_in, const int* in_sizes, int n_in,
                              void* d_out, int out_size)
{
    const float* x   = (const float*)d_in[0];
    const float* pe  = (const float*)d_in[1];
    const float* Wq  = (const float*)d_in[2];
    const float* bq  = (const float*)d_in[3];
    const float* Wk  = (const float*)d_in[4];
    const float* bk  = (const float*)d_in[5];
    const float* Wv  = (const float*)d_in[6];
    const float* bv  = (const float*)d_in[7];
    const float* Wr  = (const float*)d_in[8];
    const float* br  = (const float*)d_in[9];
    const float* cb  = (const float*)d_in[10];
    const float* pb  = (const float*)d_in[11];
    const float* Wc  = (const float*)d_in[12];
    const float* bc  = (const float*)d_in[13];
    const float* W1  = (const float*)d_in[14];
    const float* b1  = (const float*)d_in[15];
    const float* W2  = (const float*)d_in[16];
    const float* b2  = (const float*)d_in[17];
    const float* lnw = (const float*)d_in[18];
    const float* lnb = (const float*)d_in[19];
    float* out = (float*)d_out;

    uint32_t *qcP, *qpP, *kP, *vP, *rP, *xbP, *pebP, *wallP, *wcbP, *w1bP, *w2bP;
    float *attnP, *t1P, *aP, *h2P;
    cudaGetSymbolAddress((void**)&qcP,   g_qc);
    cudaGetSymbolAddress((void**)&qpP,   g_qp);
    cudaGetSymbolAddress((void**)&kP,    g_k);
    cudaGetSymbolAddress((void**)&vP,    g_v);
    cudaGetSymbolAddress((void**)&rP,    g_r);
    cudaGetSymbolAddress((void**)&xbP,   g_xb);
    cudaGetSymbolAddress((void**)&pebP,  g_peb);
    cudaGetSymbolAddress((void**)&wallP, g_wqkvr);
    cudaGetSymbolAddress((void**)&attnP, g_attn);
    cudaGetSymbolAddress((void**)&t1P,   g_t1);
    cudaGetSymbolAddress((void**)&aP,    g_a);
    cudaGetSymbolAddress((void**)&h2P,   g_h2);
    cudaGetSymbolAddress((void**)&wcbP,  g_wcb);
    cudaGetSymbolAddress((void**)&w1bP,  g_w1b);
    cudaGetSymbolAddress((void**)&w2bP,  g_w2b);
    uint32_t* attw = (uint32_t*)attnP;

    const dim3 gBig(H_ / 128, M_ / 128);   // (4, 64)

    cvt_w_kernel<<<512, 256>>>(Wc, W1, W2, wcbP, w1bP, w2bP);
    cvt_x_kernel<<<(M_ * HW + L_ * HW) / 256, 256>>>(x, pe, xbP, pebP);
    cvt_wqkvr_kernel<<<2048, 256>>>(Wq, Wk, Wv, Wr, wallP);

    cudaFuncSetAttribute(projb_kernel, cudaFuncAttributeMaxDynamicSharedMemorySize, GB_SMEM_BYTES);
    projb_kernel<<<832, 256, GB_SMEM_BYTES>>>(xbP, pebP, wallP, bq, bk, bv, br, cb, pb,
                                              qcP, qpP, kP, vP, rP);

    cudaFuncSetAttribute(attn_kernel, cudaFuncAttributeMaxDynamicSharedMemorySize, ATTN_SMEM_BYTES);
    attn_kernel<<<dim3(L_ / 64, B_ * N_), 256, ATTN_SMEM_BYTES>>>(qcP, qpP, kP, vP, rP, attw);

    cudaFuncSetAttribute(gemm_bf16_kernel<GEPI_F32>,
                         cudaFuncAttributeMaxDynamicSharedMemorySize, GB_SMEM_BYTES);
    cudaFuncSetAttribute(gemm_bf16_kernel<GEPI_GELU_BF>,
                         cudaFuncAttributeMaxDynamicSharedMemorySize, GB_SMEM_BYTES);

    gemm_bf16_kernel<GEPI_F32><<<gBig, 256, GB_SMEM_BYTES>>>(attw, wcbP, bc, t1P);
    ln_kernel<<<M_, 256>>>(t1P, x, lnw, lnb, aP, qcP);

    gemm_bf16_kernel<GEPI_GELU_BF><<<gBig, 256, GB_SMEM_BYTES>>>(qcP, w1bP, b1, kP);
    gemm_bf16_kernel<GEPI_F32><<<gBig, 256, GB_SMEM_BYTES>>>(kP, w2bP, b2, h2P);
    ln_kernel<<<M_, 256>>>(aP, h2P, lnw, lnb, out, nullptr);
}